// round 1
// baseline (speedup 1.0000x reference)
#include <cuda_runtime.h>
#include <math.h>

#define BATCH 4
#define SEQ   2048
#define EMB   256
#define HEADS 8
#define HDIM  32
#define KSEL  204        /* int(2048*0.1) */
#define KSEL_PAD 208
#define TILE  64
#define KCH   16

/* ------------ scratch (no allocations allowed) ------------ */
__device__ float g_scores[(size_t)BATCH * SEQ * SEQ];   /* 67 MB */
__device__ int   g_idx[BATCH * SEQ * KSEL];
__device__ float g_q[(size_t)BATCH * SEQ * EMB];
__device__ float g_k[(size_t)BATCH * SEQ * EMB];
__device__ float g_v[(size_t)BATCH * SEQ * EMB];
__device__ float g_ctx[(size_t)BATCH * SEQ * EMB];

/* ------------ fast exp on the FMA pipe (avoids MUFU) ------------ */
__device__ __forceinline__ float fexp(float x) {
    float y = x * 1.4426950408889634f;          /* log2(e) */
    if (y < -126.0f) return 0.0f;
    float n = floorf(y);
    float f = y - n;
    float p = 1.33988744e-3f;
    p = fmaf(p, f, 9.61843735e-3f);
    p = fmaf(p, f, 5.55033250e-2f);
    p = fmaf(p, f, 2.40226448e-1f);
    p = fmaf(p, f, 6.93147202e-1f);
    p = fmaf(p, f, 1.0f);
    return p * __int_as_float(((int)n + 127) << 23);
}

/* ------------ generic C = alpha * A[M,K] * B[N,K]^T (+bias), batched ------------ */
__global__ __launch_bounds__(256) void gemm_abt(
    const float* __restrict__ A, const float* __restrict__ B,
    float* __restrict__ C, const float* __restrict__ bias,
    int N, int K, float alpha,
    size_t sA, size_t sB, size_t sC)
{
    A += (size_t)blockIdx.z * sA;
    B += (size_t)blockIdx.z * sB;
    C += (size_t)blockIdx.z * sC;

    __shared__ float As[KCH][TILE + 4];
    __shared__ float Bs[KCH][TILE + 4];

    int tid = threadIdx.x;
    int tx = tid & 15, ty = tid >> 4;
    int row0 = blockIdx.y * TILE, col0 = blockIdx.x * TILE;

    int lr = tid >> 2;            /* 0..63 */
    int lk = (tid & 3) * 4;       /* 0,4,8,12 */
    const float* Aload = A + (size_t)(row0 + lr) * K + lk;
    const float* Bload = B + (size_t)(col0 + lr) * K + lk;

    float acc[4][4] = {};

    for (int kk = 0; kk < K; kk += KCH) {
        float4 av = *(const float4*)(Aload + kk);
        float4 bv = *(const float4*)(Bload + kk);
        As[lk + 0][lr] = av.x; As[lk + 1][lr] = av.y;
        As[lk + 2][lr] = av.z; As[lk + 3][lr] = av.w;
        Bs[lk + 0][lr] = bv.x; Bs[lk + 1][lr] = bv.y;
        Bs[lk + 2][lr] = bv.z; Bs[lk + 3][lr] = bv.w;
        __syncthreads();
#pragma unroll
        for (int k = 0; k < KCH; k++) {
            float4 a = *(const float4*)&As[k][ty * 4];
            float4 b = *(const float4*)&Bs[k][tx * 4];
            float ar[4] = {a.x, a.y, a.z, a.w};
            float br[4] = {b.x, b.y, b.z, b.w};
#pragma unroll
            for (int i = 0; i < 4; i++)
#pragma unroll
                for (int j = 0; j < 4; j++)
                    acc[i][j] = fmaf(ar[i], br[j], acc[i][j]);
        }
        __syncthreads();
    }

#pragma unroll
    for (int i = 0; i < 4; i++) {
        float4 o;
        float b0 = 0.f, b1 = 0.f, b2 = 0.f, b3 = 0.f;
        if (bias) {
            b0 = bias[col0 + tx * 4 + 0];
            b1 = bias[col0 + tx * 4 + 1];
            b2 = bias[col0 + tx * 4 + 2];
            b3 = bias[col0 + tx * 4 + 3];
        }
        o.x = fmaf(alpha, acc[i][0], b0);
        o.y = fmaf(alpha, acc[i][1], b1);
        o.z = fmaf(alpha, acc[i][2], b2);
        o.w = fmaf(alpha, acc[i][3], b3);
        *(float4*)(C + (size_t)(row0 + ty * 4 + i) * N + col0 + tx * 4) = o;
    }
}

/* ------------ exact per-row top-k (radix select, ties by ascending index) ------------ */
__global__ __launch_bounds__(256) void topk_kernel(
    const float* __restrict__ scores, int* __restrict__ idx)
{
    int row = blockIdx.x;                 /* 0..8191 */
    int tid = threadIdx.x;
    __shared__ unsigned int u[SEQ];
    __shared__ unsigned int hist[256];
    __shared__ unsigned int bc[2];
    __shared__ unsigned int thcnt[256];
    __shared__ unsigned int cnt;

    const float* srow = scores + (size_t)row * SEQ;
    for (int t = tid; t < SEQ; t += 256) {
        unsigned int bits = __float_as_uint(srow[t]);
        u[t] = bits ^ ((bits & 0x80000000u) ? 0xFFFFFFFFu : 0x80000000u);
    }
    if (tid == 0) cnt = 0;

    unsigned int remaining = KSEL;
    unsigned int prefix = 0;

    for (int shift = 24; shift >= 0; shift -= 8) {
        unsigned int himask = (shift == 24) ? 0u : (0xFFFFFFFFu << (shift + 8));
        hist[tid] = 0;
        __syncthreads();
        for (int t = tid; t < SEQ; t += 256) {
            unsigned int val = u[t];
            if ((val & himask) == prefix)
                atomicAdd(&hist[(val >> shift) & 255u], 1u);
        }
        __syncthreads();
        if (tid == 0) {
            unsigned int cum = 0, sel = 0;
            for (int b = 255; b >= 0; b--) {
                unsigned int c = hist[b];
                if (cum + c >= remaining) { sel = (unsigned int)b; break; }
                cum += c;
            }
            bc[0] = prefix | (sel << shift);
            bc[1] = remaining - cum;
        }
        __syncthreads();
        prefix = bc[0];
        remaining = bc[1];
        __syncthreads();
    }

    unsigned int T = prefix;                    /* exact k-th largest key */
    unsigned int ties_allowed = remaining;
    unsigned int gbase = KSEL - remaining;      /* # strictly greater */

    /* strictly greater: any order */
    for (int t = tid; t < SEQ; t += 256) {
        if (u[t] > T) {
            unsigned int slot = atomicAdd(&cnt, 1u);
            idx[(size_t)row * KSEL + slot] = t;
        }
    }

    /* ties: blocked ownership -> ascending index order */
    int base = tid * 8;
    unsigned int local = 0;
#pragma unroll
    for (int i = 0; i < 8; i++) if (u[base + i] == T) local++;
    thcnt[tid] = local;
    for (int off = 1; off < 256; off <<= 1) {
        __syncthreads();
        unsigned int vv = (tid >= off) ? thcnt[tid - off] : 0u;
        __syncthreads();
        thcnt[tid] += vv;
    }
    __syncthreads();
    unsigned int r = thcnt[tid] - local;        /* exclusive prefix */
#pragma unroll
    for (int i = 0; i < 8; i++) {
        if (u[base + i] == T) {
            if (r < ties_allowed)
                idx[(size_t)row * KSEL + gbase + r] = base + i;
            r++;
        }
    }
}

/* ------------ fused sparse attention: logits, softmax, ctx, attn row ------------ */
__global__ __launch_bounds__(256) void sparse_attn_kernel(
    const float* __restrict__ q, const float* __restrict__ k,
    const float* __restrict__ v, const int* __restrict__ idx,
    float* __restrict__ ctx, float* __restrict__ attn_out)
{
    int row = blockIdx.x;          /* b*SEQ + s */
    int b = row >> 11;
    int tid = threadIdx.x;

    __shared__ float qs[EMB];
    __shared__ int   sidx[KSEL_PAD];
    __shared__ float lg[HEADS][KSEL_PAD];
    __shared__ float rowbuf[SEQ];

    qs[tid] = q[(size_t)row * EMB + tid];
    if (tid < KSEL) sidx[tid] = idx[(size_t)row * KSEL + tid];
    __syncthreads();

    /* phase 1: logits at selected columns, all 8 heads per thread */
    if (tid < KSEL) {
        int t = sidx[tid];
        const float4* kr = (const float4*)(k + ((size_t)(b * SEQ + t)) * EMB);
#pragma unroll
        for (int h = 0; h < HEADS; h++) {
            float acc = 0.f;
#pragma unroll
            for (int d4 = 0; d4 < 8; d4++) {
                float4 kk = kr[h * 8 + d4];
                const float* qh = &qs[h * HDIM + d4 * 4];
                acc = fmaf(kk.x, qh[0], acc);
                acc = fmaf(kk.y, qh[1], acc);
                acc = fmaf(kk.z, qh[2], acc);
                acc = fmaf(kk.w, qh[3], acc);
            }
            lg[h][tid] = acc * 0.17677669529663687f;   /* 1/sqrt(32) */
        }
    }
    __syncthreads();

    /* phase 2: per-head softmax (one warp per head) */
    {
        int h = tid >> 5, lane = tid & 31;
        float m = -1e30f;
        for (int j = lane; j < KSEL; j += 32) m = fmaxf(m, lg[h][j]);
#pragma unroll
        for (int o = 16; o; o >>= 1) m = fmaxf(m, __shfl_xor_sync(0xffffffffu, m, o));
        float s = 0.f;
        for (int j = lane; j < KSEL; j += 32) {
            float e = fexp(lg[h][j] - m);
            lg[h][j] = e;
            s += e;
        }
#pragma unroll
        for (int o = 16; o; o >>= 1) s += __shfl_xor_sync(0xffffffffu, s, o);
        float inv = 1.f / s;
        for (int j = lane; j < KSEL; j += 32) lg[h][j] *= inv;
    }
    __syncthreads();

    /* phase 3: ctx[d] = sum_j p[h(d)][j] * v[t_j, d]   (thread = dim) */
    {
        int hh = tid >> 5;
        float acc = 0.f;
        const float* vb = v + (size_t)b * SEQ * EMB + tid;
#pragma unroll 4
        for (int j = 0; j < KSEL; j++)
            acc = fmaf(lg[hh][j], vb[(size_t)sidx[j] * EMB], acc);
        ctx[(size_t)row * EMB + tid] = acc;
    }

    /* phase 4: attn_weights row = head-mean of probs, scattered into zeros */
    for (int t0 = tid; t0 < SEQ; t0 += 256) rowbuf[t0] = 0.f;
    __syncthreads();
    if (tid < KSEL) {
        float pm = 0.f;
#pragma unroll
        for (int hh = 0; hh < HEADS; hh++) pm += lg[hh][tid];
        rowbuf[sidx[tid]] = pm * 0.125f;
    }
    __syncthreads();
    float4* dst = (float4*)(attn_out + (size_t)row * SEQ);
    const float4* src = (const float4*)rowbuf;
    for (int t0 = tid; t0 < SEQ / 4; t0 += 256) dst[t0] = src[t0];
}

/* ------------ launch ------------ */
extern "C" void kernel_launch(void* const* d_in, const int* in_sizes, int n_in,
                              void* d_out, int out_size)
{
    const float* x  = (const float*)d_in[0];
    const float* Wq = (const float*)d_in[1];
    const float* bq = (const float*)d_in[2];
    const float* Wk = (const float*)d_in[3];
    const float* bk = (const float*)d_in[4];
    const float* Wv = (const float*)d_in[5];
    const float* bv = (const float*)d_in[6];
    const float* Wo = (const float*)d_in[7];
    const float* bo = (const float*)d_in[8];

    float* out  = (float*)d_out;
    float* attn = out + (size_t)BATCH * SEQ * EMB;

    float *scores, *q, *k, *v, *ctx;
    int* idx;
    cudaGetSymbolAddress((void**)&scores, g_scores);
    cudaGetSymbolAddress((void**)&idx,    g_idx);
    cudaGetSymbolAddress((void**)&q,      g_q);
    cudaGetSymbolAddress((void**)&k,      g_k);
    cudaGetSymbolAddress((void**)&v,      g_v);
    cudaGetSymbolAddress((void**)&ctx,    g_ctx);

    /* 1. scores = x @ x^T / 16  (per batch) */
    gemm_abt<<<dim3(SEQ / TILE, SEQ / TILE, BATCH), 256>>>(
        x, x, scores, nullptr, SEQ, EMB, 0.0625f,
        (size_t)SEQ * EMB, (size_t)SEQ * EMB, (size_t)SEQ * SEQ);

    /* 2. exact top-k index selection per row */
    topk_kernel<<<BATCH * SEQ, 256>>>(scores, idx);

    /* 3. q/k/v projections: [8192,256] @ W^T */
    gemm_abt<<<dim3(EMB / TILE, (BATCH * SEQ) / TILE, 1), 256>>>(
        x, Wq, q, bq, EMB, EMB, 1.0f, 0, 0, 0);
    gemm_abt<<<dim3(EMB / TILE, (BATCH * SEQ) / TILE, 1), 256>>>(
        x, Wk, k, bk, EMB, EMB, 1.0f, 0, 0, 0);
    gemm_abt<<<dim3(EMB / TILE, (BATCH * SEQ) / TILE, 1), 256>>>(
        x, Wv, v, bv, EMB, EMB, 1.0f, 0, 0, 0);

    /* 4. fused sparse attention + attn_weights output */
    sparse_attn_kernel<<<BATCH * SEQ, 256>>>(q, k, v, idx, ctx, attn);

    /* 5. out = ctx @ Wo^T */
    gemm_abt<<<dim3(EMB / TILE, (BATCH * SEQ) / TILE, 1), 256>>>(
        ctx, Wo, out, bo, EMB, EMB, 1.0f, 0, 0, 0);
}